// round 2
// baseline (speedup 1.0000x reference)
#include <cuda_runtime.h>

#define NEGV -1.0e8f
#define Nn   1024
#define T    64
#define Gt   16            // tiles per dimension
#define WAVES (2*Gt - 1)   // 31
#define VW   1025          // V array is (N+1) x (M+1)

// Global V lattice in log space, 4 states per cell (float4). 16.8 MB scratch.
__device__ float4 VG[VW * VW];

// ---------------------------------------------------------------------------
// Init: V[0][j] = V[i][0] = NEG for all states, V[0][0] = 0 for all states.
// ---------------------------------------------------------------------------
__global__ void init_kernel() {
    int j = blockIdx.x * 256 + threadIdx.x;
    if (j < VW) {
        float4 neg = make_float4(NEGV, NEGV, NEGV, NEGV);
        VG[j] = neg;            // row 0
        VG[j * VW] = neg;       // col 0
        if (j == 0) VG[0] = make_float4(0.f, 0.f, 0.f, 0.f);
    }
}

// ---------------------------------------------------------------------------
// One wave of independent 64x64 tiles. 256 threads = (cell a, state t),
// a = tid>>2 in [0,64), t = tid&3. One __syncthreads per diagonal.
// ---------------------------------------------------------------------------
__global__ __launch_bounds__(256) void wave_kernel(const float* __restrict__ theta,
                                                   const float4* __restrict__ A4,
                                                   int wave) {
    __shared__ float4 th[T + 1];          // top halo: th[k] = V[i0-1][j0-1+k]
    __shared__ float4 lh[T];              // left halo: lh[a] = V[i0+a][j0-1]
    __shared__ float4 B0[T + 2], B1[T + 2], B2[T + 2];   // rolling diagonals

    int Ilo = (wave - (Gt - 1) < 0) ? 0 : wave - (Gt - 1);
    int I = Ilo + blockIdx.x;
    int J = wave - I;
    int i0 = I * T + 1, j0 = J * T + 1;   // global (i,j) of tile origin cell

    int tid = threadIdx.x;
    int a = tid >> 2;
    int t = tid & 3;

    float4 neg4 = make_float4(NEGV, NEGV, NEGV, NEGV);
    if (tid < T + 2) { B0[tid] = neg4; B1[tid] = neg4; B2[tid] = neg4; }
    if (tid < T + 1) {
        th[tid] = VG[(i0 - 1) * VW + (j0 - 1) + tid];
    } else if (tid < 2 * T + 1) {
        int k = tid - (T + 1);
        lh[k] = VG[(i0 + k) * VW + (j0 - 1)];
    }
    __syncthreads();
    if (tid == 0) B0[0] = th[0];   // seed: diag(-2) slot 0 = corner

    float4* Dm2 = B0;   // diagonal e-2
    float4* Dm1 = B1;   // diagonal e-1
    float4* Dn  = B2;   // diagonal e (output)

    const int ri = i0 - 1 + a;     // fixed theta/A row for this thread

    // 4-deep register prefetch ring for A (float4) + theta (scalar).
    float4 Ab[4];
    float  tb[4];
    auto LD = [&](int e, float4& Adst, float& tdst) {
        int c = j0 - 1 + e - a;                       // theta/A column
        c = c < 0 ? 0 : (c > Nn - 1 ? Nn - 1 : c);    // clamp (garbage if invalid)
        int idx = (ri * Nn + c) * 4 + t;
        Adst = A4[idx];
        tdst = theta[idx];
    };
    LD(0, Ab[0], tb[0]); LD(1, Ab[1], tb[1]);
    LD(2, Ab[2], tb[2]); LD(3, Ab[3], tb[3]);

    #pragma unroll 4
    for (int e = 0; e < 2 * T - 1; ++e) {
        // Seed halo cells into the e-1 diagonal buffer (disjoint slots, no race).
        if (e < T) {
            if (tid == 0)  Dm1[0]     = th[e + 1];   // V(-1, e)
            if (tid == 32) Dm1[e + 1] = lh[e];       // V(e, -1)
        }
        __syncthreads();

        int amin = (e - (T - 1) < 0) ? 0 : e - (T - 1);
        int amax = (e < T - 1) ? e : T - 1;
        bool valid = (a >= amin) && (a <= amax);

        int slot = e & 3;
        float4 Av = Ab[slot];
        float  tv = tb[slot];

        // source vector per target: t=0(m),3(s): V[i-1,j-1]; t=1(x): V[i-1,j]; t=2(y): V[i,j-1]
        const float4* sp = (t == 1) ? (Dm1 + a)
                         : (t == 2) ? (Dm1 + a + 1)
                                    : (Dm2 + a);
        float4 s4 = *sp;

        float w0 = s4.x + Av.x;
        float w1 = s4.y + Av.y;
        float w2 = s4.z + Av.z;
        float w3 = s4.w + Av.w;
        float m = fmaxf(fmaxf(w0, w1), fmaxf(w2, w3));
        float sum = __expf(w0 - m) + __expf(w1 - m) + __expf(w2 - m) + __expf(w3 - m);
        float r = m + __logf(sum) + tv;

        // refill this slot with data for diagonal e+4 (distance-4 prefetch)
        LD(e + 4, Ab[slot], tb[slot]);

        if (valid) {
            ((float*)(Dn + (a + 1)))[t] = r;
            int b = e - a;
            if (a == T - 1 || b == T - 1) {
                ((float*)(VG + (i0 + a) * VW + (j0 + b)))[t] = r;  // boundary for neighbors
            }
        }

        float4* tmp = Dm2; Dm2 = Dm1; Dm1 = Dn; Dn = tmp;
    }
}

// ---------------------------------------------------------------------------
// Final: out = logsumexp(V[N][M][:])
// ---------------------------------------------------------------------------
__global__ void final_kernel(float* out) {
    float4 v = VG[Nn * VW + Nn];
    float m = fmaxf(fmaxf(v.x, v.y), fmaxf(v.z, v.w));
    out[0] = m + __logf(__expf(v.x - m) + __expf(v.y - m) +
                        __expf(v.z - m) + __expf(v.w - m));
}

// ---------------------------------------------------------------------------
extern "C" void kernel_launch(void* const* d_in, const int* in_sizes, int n_in,
                              void* d_out, int out_size) {
    const float*  theta = (const float*)d_in[0];   // [1024,1024,4]
    const float4* A4    = (const float4*)d_in[1];  // [1024,1024,4,4] -> float4 per target

    init_kernel<<<(VW + 255) / 256, 256>>>();

    for (int w = 0; w < WAVES; ++w) {
        int Ilo = (w - (Gt - 1) < 0) ? 0 : w - (Gt - 1);
        int Ihi = (w < Gt - 1) ? w : Gt - 1;
        wave_kernel<<<Ihi - Ilo + 1, 256>>>(theta, A4, w);
    }

    final_kernel<<<1, 1>>>((float*)d_out);
}